// round 14
// baseline (speedup 1.0000x reference)
#include <cuda_runtime.h>
#include <cuda_fp16.h>
#include <cstdint>

#define N_USERS 100000
#define N_ITEMS 40000
#define DIM     64
#define NTOT    (N_USERS + N_ITEMS)
#define VPR     16                 // float4 per row
#define HPR     8                  // uint4 (8 halves each) per fp16 row
#define NNZ_UI_MAX 1500000
#define NNZ_II_MAX 1000000
#define NNZ_UU_MAX 1500000

#define RPB  32                    // rows per 256-thread block (8 lanes/row)
#define B_II (N_ITEMS / RPB)       // 1250
#define B_UU (N_USERS / RPB)       // 3125
#define B_UI (NTOT   / RPB)        // 4375

// scan tiling
#define SCAN_TILE 2048
#define NB_UI ((NTOT + 1 + SCAN_TILE - 1) / SCAN_TILE)     // 69
#define NB_II ((N_ITEMS + 1 + SCAN_TILE - 1) / SCAN_TILE)  // 20
#define NB_UU ((N_USERS + 1 + SCAN_TILE - 1) / SCAN_TILE)  // 49
#define NB_ALL (NB_UI + NB_II + NB_UU)                     // 138

// -------- scratch (allocation-free: __device__ globals) --------
__device__ uint4  g_iih [N_ITEMS * HPR];
__device__ uint4  g_uuh [N_USERS * HPR];
__device__ uint4  g_ii1h[N_ITEMS * HPR];
__device__ uint4  g_uu1h[N_USERS * HPR];
__device__ uint4  g_egoh_a[NTOT * HPR];   // ego0, later e2
__device__ uint4  g_egoh_b[NTOT * HPR];   // e1

__device__ int    g_ptr_ui[NTOT + 1];
__device__ float2 g_pk_ui[NNZ_UI_MAX];   // (.x = int bits of col*HPR, .y = val)
__device__ int    g_rk_ui[NNZ_UI_MAX];
__device__ int    g_ptr_ii[N_ITEMS + 1];
__device__ float2 g_pk_ii[NNZ_II_MAX];
__device__ int    g_rk_ii[NNZ_II_MAX];
__device__ int    g_ptr_uu[N_USERS + 1];
__device__ float2 g_pk_uu[NNZ_UU_MAX];
__device__ int    g_rk_uu[NNZ_UU_MAX];
__device__ int    g_bsum[NB_ALL];
__device__ unsigned int g_arr[3];   // monotonic arrival counters (per matrix)
__device__ unsigned int g_dn[3];    // monotonic epoch flags (per matrix)

// -------- helpers --------
__device__ __forceinline__ uint4 pack8(float4 a, float4 b) {
    uint4 o;
    __half2* h = (__half2*)&o;
    h[0] = __float22half2_rn(make_float2(a.x, a.y));
    h[1] = __float22half2_rn(make_float2(a.z, a.w));
    h[2] = __float22half2_rn(make_float2(b.x, b.y));
    h[3] = __float22half2_rn(make_float2(b.z, b.w));
    return o;
}

__device__ __forceinline__ void fma8(float* s, uint4 g, float w) {
    const __half2* h = (const __half2*)&g;
    float2 f0 = __half22float2(h[0]);
    float2 f1 = __half22float2(h[1]);
    float2 f2 = __half22float2(h[2]);
    float2 f3 = __half22float2(h[3]);
    s[0] += w * f0.x; s[1] += w * f0.y; s[2] += w * f1.x; s[3] += w * f1.y;
    s[4] += w * f2.x; s[5] += w * f2.y; s[6] += w * f3.x; s[7] += w * f3.y;
}

// 8 lanes/row; lane c holds halves [8c, 8c+8).  Unroll 4 (R6/R8-proven).
__device__ __forceinline__ void spmm_row_h(const int* __restrict__ ptr,
                                           const float2* __restrict__ pk,
                                           const uint4* __restrict__ xh,
                                           int r, int c, float* s) {
    #pragma unroll
    for (int k = 0; k < 8; ++k) s[k] = 0.f;
    int j = __ldg(ptr + r);
    int end = __ldg(ptr + r + 1);
    for (; j + 4 <= end; j += 4) {
        float2 p0 = __ldg(pk + j + 0);
        float2 p1 = __ldg(pk + j + 1);
        float2 p2 = __ldg(pk + j + 2);
        float2 p3 = __ldg(pk + j + 3);
        uint4 g0 = __ldg(xh + __float_as_int(p0.x) + c);
        uint4 g1 = __ldg(xh + __float_as_int(p1.x) + c);
        uint4 g2 = __ldg(xh + __float_as_int(p2.x) + c);
        uint4 g3 = __ldg(xh + __float_as_int(p3.x) + c);
        fma8(s, g0, p0.y); fma8(s, g1, p1.y); fma8(s, g2, p2.y); fma8(s, g3, p3.y);
    }
    for (; j < end; ++j) {
        float2 p = __ldg(pk + j);
        uint4 g = __ldg(xh + __float_as_int(p.x) + c);
        fma8(s, g, p.y);
    }
}

__device__ __forceinline__ void store_h(uint4* __restrict__ yh, int r, int c,
                                        const float* s) {
    uint4 o;
    __half2* h = (__half2*)&o;
    h[0] = __float22half2_rn(make_float2(s[0], s[1]));
    h[1] = __float22half2_rn(make_float2(s[2], s[3]));
    h[2] = __float22half2_rn(make_float2(s[4], s[5]));
    h[3] = __float22half2_rn(make_float2(s[6], s[7]));
    yh[(size_t)r * HPR + c] = o;
}

__device__ __forceinline__ void store_f(float4* __restrict__ y, int r, int c,
                                        const float* s) {
    size_t b = (size_t)r * VPR + 2 * c;
    y[b]     = make_float4(s[0], s[1], s[2], s[3]);
    y[b + 1] = make_float4(s[4], s[5], s[6], s[7]);
}

// -------- convert inputs to fp16 (no ptr zeroing — chains do their own) ------
#define CVT_EGO (NTOT   * HPR)     // 1.12M  (largest)
#define CVT_II  (N_ITEMS * HPR)
#define CVT_UU  (N_USERS * HPR)

__global__ __launch_bounds__(256) void k_cvt(const float4* __restrict__ u,
                                             const float4* __restrict__ it,
                                             const float4* __restrict__ ii,
                                             const float4* __restrict__ uu,
                                             uint4* __restrict__ egoh,
                                             uint4* __restrict__ iih,
                                             uint4* __restrict__ uuh) {
    int i = blockIdx.x * 256 + threadIdx.x;
    if (i < CVT_EGO) {
        float4 a0, a1;
        if (i < N_USERS * HPR) {
            a0 = __ldg(u + 2 * i); a1 = __ldg(u + 2 * i + 1);
        } else {
            int t = 2 * i - N_USERS * VPR;
            a0 = __ldg(it + t); a1 = __ldg(it + t + 1);
        }
        egoh[i] = pack8(a0, a1);
    }
    if (i < CVT_II) iih[i] = pack8(__ldg(ii + 2 * i), __ldg(ii + 2 * i + 1));
    if (i < CVT_UU) uuh[i] = pack8(__ldg(uu + 2 * i), __ldg(uu + 2 * i + 1));
}

__global__ __launch_bounds__(256) void k_zero1(int* __restrict__ p, int n) {
    int i = blockIdx.x * 256 + threadIdx.x;
    if (i < n) p[i] = 0;
}

// histogram + per-edge within-row rank; 2 edges/thread
__global__ __launch_bounds__(256) void k_hist(const int* __restrict__ rows, int n,
                                              int* __restrict__ cnt,
                                              int* __restrict__ rk) {
    int base = blockIdx.x * 512 + threadIdx.x;
    #pragma unroll
    for (int u = 0; u < 2; ++u) {
        int i = base + u * 256;
        if (i < n) rk[i] = atomicAdd(cnt + __ldg(rows + i), 1);
    }
}

// grid-resident single-kernel exclusive scan of one array (nb <= 69 blocks).
// Monotonic epoch counters -> deterministic + graph-replay safe.
__global__ __launch_bounds__(1024) void k_scan_one(int* __restrict__ cnt, int n,
                                                   int* __restrict__ bsum,
                                                   unsigned int* __restrict__ arr,
                                                   unsigned int* __restrict__ done,
                                                   int nb) {
    int b = blockIdx.x;
    int base = b * SCAN_TILE;
    int t = threadIdx.x;
    int i0 = base + 2 * t, i1 = base + 2 * t + 1;
    int x0 = (i0 < n) ? cnt[i0] : 0;
    int x1 = (i1 < n) ? cnt[i1] : 0;
    int pair = x0 + x1;

    __shared__ int sh[1024];
    sh[t] = pair;
    __syncthreads();
    #pragma unroll
    for (int off = 1; off < 1024; off <<= 1) {
        int v = (t >= off) ? sh[t - off] : 0;
        __syncthreads();
        sh[t] += v;
        __syncthreads();
    }
    int excl = sh[t] - pair;

    if (t == 1023) {
        bsum[b] = sh[1023];
        __threadfence();
    }
    __syncthreads();

    __shared__ unsigned int s_old;
    if (t == 0) s_old = atomicAdd(arr, 1u);
    __syncthreads();
    unsigned int old = s_old;
    unsigned int epoch = old / (unsigned)nb;
    bool last = (old % (unsigned)nb) == (unsigned)(nb - 1);

    if (last) {
        if (t < 32) {
            int carry = 0;
            for (int bb = 0; bb < nb; bb += 32) {
                int i = bb + t;
                int v = (i < nb) ? __ldcg(bsum + i) : 0;
                int incl = v;
                #pragma unroll
                for (int o = 1; o < 32; o <<= 1) {
                    int u = __shfl_up_sync(0xffffffffu, incl, o);
                    if (t >= o) incl += u;
                }
                if (i < nb) bsum[i] = incl - v + carry;
                carry += __shfl_sync(0xffffffffu, incl, 31);
            }
            __threadfence();
        }
        __syncthreads();
        if (t == 0) atomicExch(done, epoch + 1u);
    }

    if (t == 0) {
        while (atomicAdd(done, 0u) < epoch + 1u) { __nanosleep(64); }
    }
    __syncthreads();
    __threadfence();

    int off = __ldcg(bsum + b);
    if (i0 < n) cnt[i0] = excl + off;
    if (i1 < n) cnt[i1] = excl + x0 + off;
}

// scatter without atomics: pos = ptr[row] + rank[i]; 2 edges/thread
__global__ __launch_bounds__(256) void k_scatter(const int* __restrict__ rows,
                                                 const int* __restrict__ cols,
                                                 const float* __restrict__ vals,
                                                 const int* __restrict__ ptr,
                                                 const int* __restrict__ rk,
                                                 float2* __restrict__ pk, int n) {
    int base = blockIdx.x * 512 + threadIdx.x;
    #pragma unroll
    for (int u = 0; u < 2; ++u) {
        int i = base + u * 256;
        if (i < n) {
            int pos = __ldg(ptr + __ldg(rows + i)) + __ldg(rk + i);
            pk[pos] = make_float2(__int_as_float(__ldg(cols + i) * HPR), __ldg(vals + i));
        }
    }
}

// -------- SpMM launchers --------
__global__ __launch_bounds__(256) void k_spmm_h16(const int* __restrict__ ptr,
                                                  const float2* __restrict__ pk,
                                                  const uint4* __restrict__ xh,
                                                  uint4* __restrict__ yh) {
    int r = blockIdx.x * RPB + (threadIdx.x >> 3);
    int c = threadIdx.x & 7;
    float s[8];
    spmm_row_h(ptr, pk, xh, r, c, s);
    store_h(yh, r, c, s);
}

__global__ __launch_bounds__(256) void k_spmm_f32(const int* __restrict__ ptr,
                                                  const float2* __restrict__ pk,
                                                  const uint4* __restrict__ xh,
                                                  float4* __restrict__ y) {
    int r = blockIdx.x * RPB + (threadIdx.x >> 3);
    int c = threadIdx.x & 7;
    float s[8];
    spmm_row_h(ptr, pk, xh, r, c, s);
    store_f(y, r, c, s);
}

// ui layer3 fused with finalize:
// out = (ego0 + e1 + e2 + spmm(e2))/4 + l2_normalize(g)
__global__ __launch_bounds__(256) void k_ui3(const int* __restrict__ ptr_ui,
                                             const float2* __restrict__ pk_ui,
                                             const uint4* __restrict__ e2h,   // egoh_a
                                             const uint4* __restrict__ e1h,   // egoh_b
                                             const float4* __restrict__ u_emb,
                                             const float4* __restrict__ it_emb,
                                             const float4* __restrict__ out_uu,
                                             const float4* __restrict__ out_ii,
                                             float4* __restrict__ out_u,
                                             float4* __restrict__ out_i) {
    int r = blockIdx.x * RPB + (threadIdx.x >> 3);
    int c = threadIdx.x & 7;
    float s[8];
    spmm_row_h(ptr_ui, pk_ui, e2h, r, c, s);

    size_t hidx = (size_t)r * HPR + c;
    fma8(s, __ldg(e1h + hidx), 1.0f);
    fma8(s, __ldg(e2h + hidx), 1.0f);

    const float4* e0 = (r < N_USERS) ? (u_emb + (size_t)r * VPR)
                                     : (it_emb + (size_t)(r - N_USERS) * VPR);
    float4 a0 = __ldg(e0 + 2 * c), a1 = __ldg(e0 + 2 * c + 1);
    float o0 = (a0.x + s[0]) * 0.25f, o1 = (a0.y + s[1]) * 0.25f;
    float o2 = (a0.z + s[2]) * 0.25f, o3 = (a0.w + s[3]) * 0.25f;
    float o4 = (a1.x + s[4]) * 0.25f, o5 = (a1.y + s[5]) * 0.25f;
    float o6 = (a1.z + s[6]) * 0.25f, o7 = (a1.w + s[7]) * 0.25f;

    const float4* g = (r < N_USERS) ? (out_uu + (size_t)r * VPR)
                                    : (out_ii + (size_t)(r - N_USERS) * VPR);
    float4 g0 = __ldg(g + 2 * c), g1 = __ldg(g + 2 * c + 1);
    float d = g0.x * g0.x + g0.y * g0.y + g0.z * g0.z + g0.w * g0.w
            + g1.x * g1.x + g1.y * g1.y + g1.z * g1.z + g1.w * g1.w;
    #pragma unroll
    for (int o = 4; o; o >>= 1) d += __shfl_xor_sync(0xffffffffu, d, o, 8);
    float scale = 1.0f / fmaxf(sqrtf(d), 1e-12f);

    float4* ob = (r < N_USERS) ? (out_u + (size_t)r * VPR)
                               : (out_i + (size_t)(r - N_USERS) * VPR);
    ob[2 * c]     = make_float4(o0 + g0.x * scale, o1 + g0.y * scale,
                                o2 + g0.z * scale, o3 + g0.w * scale);
    ob[2 * c + 1] = make_float4(o4 + g1.x * scale, o5 + g1.y * scale,
                                o6 + g1.z * scale, o7 + g1.w * scale);
}

// -------- host orchestration --------
static inline int gridFor(long long threads, int tpb) {
    return (int)((threads + tpb - 1) / tpb);
}

extern "C" void kernel_launch(void* const* d_in, const int* in_sizes, int n_in,
                              void* d_out, int out_size) {
    const float4* user_emb = (const float4*)d_in[0];
    const float4* item_emb = (const float4*)d_in[1];
    const float4* uu_emb   = (const float4*)d_in[2];
    const float4* ii_emb   = (const float4*)d_in[3];
    const float*  ui_vals  = (const float*)d_in[4];
    const float*  ii_vals  = (const float*)d_in[5];
    const float*  uu_vals  = (const float*)d_in[6];
    const int*    ui_rows  = (const int*)d_in[7];
    const int*    ui_cols  = (const int*)d_in[8];
    const int*    ii_rows  = (const int*)d_in[9];
    const int*    ii_cols  = (const int*)d_in[10];
    const int*    uu_rows  = (const int*)d_in[11];
    const int*    uu_cols  = (const int*)d_in[12];
    const int nnz_ui = in_sizes[7];
    const int nnz_ii = in_sizes[9];
    const int nnz_uu = in_sizes[11];

    float* out = (float*)d_out;
    float4* out_u  = (float4*)out;
    float4* out_i  = (float4*)(out + (size_t)N_USERS * DIM);
    float4* out_ii = (float4*)(out + (size_t)(N_USERS + N_ITEMS) * DIM);
    float4* out_uu = (float4*)(out + (size_t)(N_USERS + 2 * N_ITEMS) * DIM);

    uint4 *p_iih, *p_uuh, *p_ii1h, *p_uu1h, *p_egoh_a, *p_egoh_b;
    cudaGetSymbolAddress((void**)&p_iih,    g_iih);
    cudaGetSymbolAddress((void**)&p_uuh,    g_uuh);
    cudaGetSymbolAddress((void**)&p_ii1h,   g_ii1h);
    cudaGetSymbolAddress((void**)&p_uu1h,   g_uu1h);
    cudaGetSymbolAddress((void**)&p_egoh_a, g_egoh_a);
    cudaGetSymbolAddress((void**)&p_egoh_b, g_egoh_b);
    int *ptr_ui, *ptr_ii, *ptr_uu, *rk_ui, *rk_ii, *rk_uu, *bsum;
    float2 *pk_ui, *pk_ii, *pk_uu;
    unsigned int *arr, *dn;
    cudaGetSymbolAddress((void**)&ptr_ui, g_ptr_ui);
    cudaGetSymbolAddress((void**)&pk_ui,  g_pk_ui);
    cudaGetSymbolAddress((void**)&rk_ui,  g_rk_ui);
    cudaGetSymbolAddress((void**)&ptr_ii, g_ptr_ii);
    cudaGetSymbolAddress((void**)&pk_ii,  g_pk_ii);
    cudaGetSymbolAddress((void**)&rk_ii,  g_rk_ii);
    cudaGetSymbolAddress((void**)&ptr_uu, g_ptr_uu);
    cudaGetSymbolAddress((void**)&pk_uu,  g_pk_uu);
    cudaGetSymbolAddress((void**)&rk_uu,  g_rk_uu);
    cudaGetSymbolAddress((void**)&bsum,   g_bsum);
    cudaGetSymbolAddress((void**)&arr,    g_arr);
    cudaGetSymbolAddress((void**)&dn,     g_dn);

    // one-time host objects (identical launch pattern every call -> deterministic)
    static cudaStream_t sA = nullptr, sB = nullptr, sC = nullptr;
    static cudaEvent_t  eFork = nullptr, eC = nullptr, eA = nullptr, eB = nullptr;
    if (sA == nullptr) {
        cudaStreamCreateWithFlags(&sA, cudaStreamNonBlocking);
        cudaStreamCreateWithFlags(&sB, cudaStreamNonBlocking);
        cudaStreamCreateWithFlags(&sC, cudaStreamNonBlocking);
        cudaEventCreateWithFlags(&eFork, cudaEventDisableTiming);
        cudaEventCreateWithFlags(&eC, cudaEventDisableTiming);
        cudaEventCreateWithFlags(&eA, cudaEventDisableTiming);
        cudaEventCreateWithFlags(&eB, cudaEventDisableTiming);
    }

    const int TPB = 256;

    // ---- fork: A/B/C branch off the capture origin ----
    cudaEventRecord(eFork, 0);
    cudaStreamWaitEvent(sA, eFork, 0);
    cudaStreamWaitEvent(sB, eFork, 0);
    cudaStreamWaitEvent(sC, eFork, 0);

    // ---- stream C: fp16 convert (overlaps all three builds) ----
    k_cvt<<<gridFor(CVT_EGO, TPB), TPB, 0, sC>>>(user_emb, item_emb, ii_emb,
                                                 uu_emb, p_egoh_a, p_iih, p_uuh);
    cudaEventRecord(eC, sC);

    // ---- main stream: ui build starts immediately, layers wait for cvt ----
    k_zero1<<<gridFor(NTOT + 1, TPB), TPB>>>(ptr_ui, NTOT + 1);
    k_hist<<<gridFor(nnz_ui, 512), TPB>>>(ui_rows, nnz_ui, ptr_ui, rk_ui);
    k_scan_one<<<NB_UI, 1024>>>(ptr_ui, NTOT + 1, bsum, arr, dn, NB_UI);
    k_scatter<<<gridFor(nnz_ui, 512), TPB>>>(ui_rows, ui_cols, ui_vals,
                                             ptr_ui, rk_ui, pk_ui, nnz_ui);
    cudaStreamWaitEvent(0, eC, 0);
    k_spmm_h16<<<B_UI, TPB>>>(ptr_ui, pk_ui, p_egoh_a, p_egoh_b);   // ui1: e0->e1
    k_spmm_h16<<<B_UI, TPB>>>(ptr_ui, pk_ui, p_egoh_b, p_egoh_a);   // ui2: e1->e2

    // ---- stream A: ii chain ----
    k_zero1<<<gridFor(N_ITEMS + 1, TPB), TPB, 0, sA>>>(ptr_ii, N_ITEMS + 1);
    k_hist<<<gridFor(nnz_ii, 512), TPB, 0, sA>>>(ii_rows, nnz_ii, ptr_ii, rk_ii);
    k_scan_one<<<NB_II, 1024, 0, sA>>>(ptr_ii, N_ITEMS + 1, bsum + NB_UI,
                                       arr + 1, dn + 1, NB_II);
    k_scatter<<<gridFor(nnz_ii, 512), TPB, 0, sA>>>(ii_rows, ii_cols, ii_vals,
                                                    ptr_ii, rk_ii, pk_ii, nnz_ii);
    cudaStreamWaitEvent(sA, eC, 0);
    k_spmm_h16<<<B_II, TPB, 0, sA>>>(ptr_ii, pk_ii, p_iih, p_ii1h);
    k_spmm_f32<<<B_II, TPB, 0, sA>>>(ptr_ii, pk_ii, p_ii1h, out_ii);
    cudaEventRecord(eA, sA);

    // ---- stream B: uu chain ----
    k_zero1<<<gridFor(N_USERS + 1, TPB), TPB, 0, sB>>>(ptr_uu, N_USERS + 1);
    k_hist<<<gridFor(nnz_uu, 512), TPB, 0, sB>>>(uu_rows, nnz_uu, ptr_uu, rk_uu);
    k_scan_one<<<NB_UU, 1024, 0, sB>>>(ptr_uu, N_USERS + 1, bsum + NB_UI + NB_II,
                                       arr + 2, dn + 2, NB_UU);
    k_scatter<<<gridFor(nnz_uu, 512), TPB, 0, sB>>>(uu_rows, uu_cols, uu_vals,
                                                    ptr_uu, rk_uu, pk_uu, nnz_uu);
    cudaStreamWaitEvent(sB, eC, 0);
    k_spmm_h16<<<B_UU, TPB, 0, sB>>>(ptr_uu, pk_uu, p_uuh, p_uu1h);
    k_spmm_f32<<<B_UU, TPB, 0, sB>>>(ptr_uu, pk_uu, p_uu1h, out_uu);
    cudaEventRecord(eB, sB);

    // ---- join, then fused ui3 + finalize ----
    cudaStreamWaitEvent(0, eA, 0);
    cudaStreamWaitEvent(0, eB, 0);
    k_ui3<<<B_UI, TPB>>>(ptr_ui, pk_ui, p_egoh_a, p_egoh_b,
                         user_emb, item_emb, out_uu, out_ii, out_u, out_i);
}

// round 16
// speedup vs baseline: 1.0367x; 1.0367x over previous
#include <cuda_runtime.h>
#include <cuda_fp16.h>
#include <cstdint>

#define N_USERS 100000
#define N_ITEMS 40000
#define DIM     64
#define NTOT    (N_USERS + N_ITEMS)
#define VPR     16                 // float4 per row
#define HPR     8                  // uint4 (8 halves each) per fp16 row
#define NNZ_UI_MAX 1500000
#define NNZ_II_MAX 1000000
#define NNZ_UU_MAX 1500000

#define RPB  32                    // rows per 256-thread block (8 lanes/row)
#define B_II (N_ITEMS / RPB)       // 1250
#define B_UU (N_USERS / RPB)       // 3125
#define B_UI (NTOT   / RPB)        // 4375

// scan tiling
#define SCAN_TILE 2048
#define NB_UI ((NTOT + 1 + SCAN_TILE - 1) / SCAN_TILE)     // 69
#define NB_II ((N_ITEMS + 1 + SCAN_TILE - 1) / SCAN_TILE)  // 20
#define NB_UU ((N_USERS + 1 + SCAN_TILE - 1) / SCAN_TILE)  // 49
#define NB_ALL (NB_UI + NB_II + NB_UU)                     // 138

// -------- scratch (allocation-free: __device__ globals) --------
__device__ uint4  g_iih [N_ITEMS * HPR];
__device__ uint4  g_uuh [N_USERS * HPR];
__device__ uint4  g_ii1h[N_ITEMS * HPR];
__device__ uint4  g_uu1h[N_USERS * HPR];
__device__ uint4  g_egoh_a[NTOT * HPR];   // ego0, later e2
__device__ uint4  g_egoh_b[NTOT * HPR];   // e1

__device__ int    g_ptr_ui[NTOT + 1];
__device__ float2 g_pk_ui[NNZ_UI_MAX];   // (.x = int bits of col*HPR, .y = val)
__device__ int    g_rk_ui[NNZ_UI_MAX];
__device__ int    g_ptr_ii[N_ITEMS + 1];
__device__ float2 g_pk_ii[NNZ_II_MAX];
__device__ int    g_rk_ii[NNZ_II_MAX];
__device__ int    g_ptr_uu[N_USERS + 1];
__device__ float2 g_pk_uu[NNZ_UU_MAX];
__device__ int    g_rk_uu[NNZ_UU_MAX];
__device__ int    g_bsum[NB_ALL];
__device__ unsigned int g_arr[3];   // monotonic arrival counters (per matrix)
__device__ unsigned int g_dn[3];    // monotonic epoch flags (per matrix)

// -------- helpers --------
__device__ __forceinline__ uint4 pack8(float4 a, float4 b) {
    uint4 o;
    __half2* h = (__half2*)&o;
    h[0] = __float22half2_rn(make_float2(a.x, a.y));
    h[1] = __float22half2_rn(make_float2(a.z, a.w));
    h[2] = __float22half2_rn(make_float2(b.x, b.y));
    h[3] = __float22half2_rn(make_float2(b.z, b.w));
    return o;
}

__device__ __forceinline__ void fma8(float* s, uint4 g, float w) {
    const __half2* h = (const __half2*)&g;
    float2 f0 = __half22float2(h[0]);
    float2 f1 = __half22float2(h[1]);
    float2 f2 = __half22float2(h[2]);
    float2 f3 = __half22float2(h[3]);
    s[0] += w * f0.x; s[1] += w * f0.y; s[2] += w * f1.x; s[3] += w * f1.y;
    s[4] += w * f2.x; s[5] += w * f2.y; s[6] += w * f3.x; s[7] += w * f3.y;
}

// 8 lanes/row; lane c holds halves [8c, 8c+8).  Unroll 4 (R6/R8-proven).
__device__ __forceinline__ void spmm_row_h(const int* __restrict__ ptr,
                                           const float2* __restrict__ pk,
                                           const uint4* __restrict__ xh,
                                           int r, int c, float* s) {
    #pragma unroll
    for (int k = 0; k < 8; ++k) s[k] = 0.f;
    int j = __ldg(ptr + r);
    int end = __ldg(ptr + r + 1);
    for (; j + 4 <= end; j += 4) {
        float2 p0 = __ldg(pk + j + 0);
        float2 p1 = __ldg(pk + j + 1);
        float2 p2 = __ldg(pk + j + 2);
        float2 p3 = __ldg(pk + j + 3);
        uint4 g0 = __ldg(xh + __float_as_int(p0.x) + c);
        uint4 g1 = __ldg(xh + __float_as_int(p1.x) + c);
        uint4 g2 = __ldg(xh + __float_as_int(p2.x) + c);
        uint4 g3 = __ldg(xh + __float_as_int(p3.x) + c);
        fma8(s, g0, p0.y); fma8(s, g1, p1.y); fma8(s, g2, p2.y); fma8(s, g3, p3.y);
    }
    for (; j < end; ++j) {
        float2 p = __ldg(pk + j);
        uint4 g = __ldg(xh + __float_as_int(p.x) + c);
        fma8(s, g, p.y);
    }
}

__device__ __forceinline__ void store_h(uint4* __restrict__ yh, int r, int c,
                                        const float* s) {
    uint4 o;
    __half2* h = (__half2*)&o;
    h[0] = __float22half2_rn(make_float2(s[0], s[1]));
    h[1] = __float22half2_rn(make_float2(s[2], s[3]));
    h[2] = __float22half2_rn(make_float2(s[4], s[5]));
    h[3] = __float22half2_rn(make_float2(s[6], s[7]));
    yh[(size_t)r * HPR + c] = o;
}

__device__ __forceinline__ void store_f(float4* __restrict__ y, int r, int c,
                                        const float* s) {
    size_t b = (size_t)r * VPR + 2 * c;
    y[b]     = make_float4(s[0], s[1], s[2], s[3]);
    y[b + 1] = make_float4(s[4], s[5], s[6], s[7]);
}

// -------- convert inputs to fp16 + zero the three ptr arrays (R11) ----------
#define CVT_EGO (NTOT   * HPR)     // 1.12M  (largest)
#define CVT_II  (N_ITEMS * HPR)
#define CVT_UU  (N_USERS * HPR)

__global__ __launch_bounds__(256) void k_cvt(const float4* __restrict__ u,
                                             const float4* __restrict__ it,
                                             const float4* __restrict__ ii,
                                             const float4* __restrict__ uu,
                                             uint4* __restrict__ egoh,
                                             uint4* __restrict__ iih,
                                             uint4* __restrict__ uuh,
                                             int* __restrict__ ptr_ui,
                                             int* __restrict__ ptr_ii,
                                             int* __restrict__ ptr_uu) {
    int i = blockIdx.x * 256 + threadIdx.x;
    if (i < CVT_EGO) {
        float4 a0, a1;
        if (i < N_USERS * HPR) {
            a0 = __ldg(u + 2 * i); a1 = __ldg(u + 2 * i + 1);
        } else {
            int t = 2 * i - N_USERS * VPR;
            a0 = __ldg(it + t); a1 = __ldg(it + t + 1);
        }
        egoh[i] = pack8(a0, a1);
    }
    if (i < CVT_II) iih[i] = pack8(__ldg(ii + 2 * i), __ldg(ii + 2 * i + 1));
    if (i < CVT_UU) uuh[i] = pack8(__ldg(uu + 2 * i), __ldg(uu + 2 * i + 1));
    if (i < NTOT + 1)    ptr_ui[i] = 0;
    if (i < N_ITEMS + 1) ptr_ii[i] = 0;
    if (i < N_USERS + 1) ptr_uu[i] = 0;
}

// histogram + per-edge rank; 4 edges/thread via int4 vector loads
__global__ __launch_bounds__(256) void k_hist(const int* __restrict__ rows, int n,
                                              int* __restrict__ cnt,
                                              int* __restrict__ rk) {
    int q = blockIdx.x * 256 + threadIdx.x;   // quad index
    int i = q * 4;
    if (i + 4 <= n) {
        int4 r4 = __ldg((const int4*)rows + q);
        int4 k4;
        k4.x = atomicAdd(cnt + r4.x, 1);
        k4.y = atomicAdd(cnt + r4.y, 1);
        k4.z = atomicAdd(cnt + r4.z, 1);
        k4.w = atomicAdd(cnt + r4.w, 1);
        ((int4*)rk)[q] = k4;
    } else {
        for (; i < n; ++i) rk[i] = atomicAdd(cnt + __ldg(rows + i), 1);
    }
}

// grid-resident single-kernel exclusive scan of one array (nb <= 69 blocks).
// Monotonic epoch counters -> deterministic + graph-replay safe.
__global__ __launch_bounds__(1024) void k_scan_one(int* __restrict__ cnt, int n,
                                                   int* __restrict__ bsum,
                                                   unsigned int* __restrict__ arr,
                                                   unsigned int* __restrict__ done,
                                                   int nb) {
    int b = blockIdx.x;
    int base = b * SCAN_TILE;
    int t = threadIdx.x;
    int i0 = base + 2 * t, i1 = base + 2 * t + 1;
    int x0 = (i0 < n) ? cnt[i0] : 0;
    int x1 = (i1 < n) ? cnt[i1] : 0;
    int pair = x0 + x1;

    __shared__ int sh[1024];
    sh[t] = pair;
    __syncthreads();
    #pragma unroll
    for (int off = 1; off < 1024; off <<= 1) {
        int v = (t >= off) ? sh[t - off] : 0;
        __syncthreads();
        sh[t] += v;
        __syncthreads();
    }
    int excl = sh[t] - pair;

    if (t == 1023) {
        bsum[b] = sh[1023];
        __threadfence();
    }
    __syncthreads();

    __shared__ unsigned int s_old;
    if (t == 0) s_old = atomicAdd(arr, 1u);
    __syncthreads();
    unsigned int old = s_old;
    unsigned int epoch = old / (unsigned)nb;
    bool last = (old % (unsigned)nb) == (unsigned)(nb - 1);

    if (last) {
        if (t < 32) {
            int carry = 0;
            for (int bb = 0; bb < nb; bb += 32) {
                int i = bb + t;
                int v = (i < nb) ? __ldcg(bsum + i) : 0;
                int incl = v;
                #pragma unroll
                for (int o = 1; o < 32; o <<= 1) {
                    int u = __shfl_up_sync(0xffffffffu, incl, o);
                    if (t >= o) incl += u;
                }
                if (i < nb) bsum[i] = incl - v + carry;
                carry += __shfl_sync(0xffffffffu, incl, 31);
            }
            __threadfence();
        }
        __syncthreads();
        if (t == 0) atomicExch(done, epoch + 1u);
    }

    if (t == 0) {
        while (atomicAdd(done, 0u) < epoch + 1u) { __nanosleep(64); }
    }
    __syncthreads();
    __threadfence();

    int off = __ldcg(bsum + b);
    if (i0 < n) cnt[i0] = excl + off;
    if (i1 < n) cnt[i1] = excl + x0 + off;
}

// scatter without atomics: pos = ptr[row] + rank[i]; 4 edges/thread, int4 loads
__global__ __launch_bounds__(256) void k_scatter(const int* __restrict__ rows,
                                                 const int* __restrict__ cols,
                                                 const float* __restrict__ vals,
                                                 const int* __restrict__ ptr,
                                                 const int* __restrict__ rk,
                                                 float2* __restrict__ pk, int n) {
    int q = blockIdx.x * 256 + threadIdx.x;
    int i = q * 4;
    if (i + 4 <= n) {
        int4   r4 = __ldg((const int4*)rows + q);
        int4   c4 = __ldg((const int4*)cols + q);
        float4 v4 = __ldg((const float4*)vals + q);
        int4   k4 = __ldg((const int4*)rk + q);
        int p0 = __ldg(ptr + r4.x) + k4.x;
        int p1 = __ldg(ptr + r4.y) + k4.y;
        int p2 = __ldg(ptr + r4.z) + k4.z;
        int p3 = __ldg(ptr + r4.w) + k4.w;
        pk[p0] = make_float2(__int_as_float(c4.x * HPR), v4.x);
        pk[p1] = make_float2(__int_as_float(c4.y * HPR), v4.y);
        pk[p2] = make_float2(__int_as_float(c4.z * HPR), v4.z);
        pk[p3] = make_float2(__int_as_float(c4.w * HPR), v4.w);
    } else {
        for (; i < n; ++i) {
            int pos = __ldg(ptr + __ldg(rows + i)) + __ldg(rk + i);
            pk[pos] = make_float2(__int_as_float(__ldg(cols + i) * HPR), __ldg(vals + i));
        }
    }
}

// -------- SpMM launchers --------
__global__ __launch_bounds__(256) void k_spmm_h16(const int* __restrict__ ptr,
                                                  const float2* __restrict__ pk,
                                                  const uint4* __restrict__ xh,
                                                  uint4* __restrict__ yh) {
    int r = blockIdx.x * RPB + (threadIdx.x >> 3);
    int c = threadIdx.x & 7;
    float s[8];
    spmm_row_h(ptr, pk, xh, r, c, s);
    store_h(yh, r, c, s);
}

__global__ __launch_bounds__(256) void k_spmm_f32(const int* __restrict__ ptr,
                                                  const float2* __restrict__ pk,
                                                  const uint4* __restrict__ xh,
                                                  float4* __restrict__ y) {
    int r = blockIdx.x * RPB + (threadIdx.x >> 3);
    int c = threadIdx.x & 7;
    float s[8];
    spmm_row_h(ptr, pk, xh, r, c, s);
    store_f(y, r, c, s);
}

// ui layer3 fused with finalize:
// out = (ego0 + e1 + e2 + spmm(e2))/4 + l2_normalize(g)
__global__ __launch_bounds__(256) void k_ui3(const int* __restrict__ ptr_ui,
                                             const float2* __restrict__ pk_ui,
                                             const uint4* __restrict__ e2h,   // egoh_a
                                             const uint4* __restrict__ e1h,   // egoh_b
                                             const float4* __restrict__ u_emb,
                                             const float4* __restrict__ it_emb,
                                             const float4* __restrict__ out_uu,
                                             const float4* __restrict__ out_ii,
                                             float4* __restrict__ out_u,
                                             float4* __restrict__ out_i) {
    int r = blockIdx.x * RPB + (threadIdx.x >> 3);
    int c = threadIdx.x & 7;
    float s[8];
    spmm_row_h(ptr_ui, pk_ui, e2h, r, c, s);

    size_t hidx = (size_t)r * HPR + c;
    fma8(s, __ldg(e1h + hidx), 1.0f);
    fma8(s, __ldg(e2h + hidx), 1.0f);

    const float4* e0 = (r < N_USERS) ? (u_emb + (size_t)r * VPR)
                                     : (it_emb + (size_t)(r - N_USERS) * VPR);
    float4 a0 = __ldg(e0 + 2 * c), a1 = __ldg(e0 + 2 * c + 1);
    float o0 = (a0.x + s[0]) * 0.25f, o1 = (a0.y + s[1]) * 0.25f;
    float o2 = (a0.z + s[2]) * 0.25f, o3 = (a0.w + s[3]) * 0.25f;
    float o4 = (a1.x + s[4]) * 0.25f, o5 = (a1.y + s[5]) * 0.25f;
    float o6 = (a1.z + s[6]) * 0.25f, o7 = (a1.w + s[7]) * 0.25f;

    const float4* g = (r < N_USERS) ? (out_uu + (size_t)r * VPR)
                                    : (out_ii + (size_t)(r - N_USERS) * VPR);
    float4 g0 = __ldg(g + 2 * c), g1 = __ldg(g + 2 * c + 1);
    float d = g0.x * g0.x + g0.y * g0.y + g0.z * g0.z + g0.w * g0.w
            + g1.x * g1.x + g1.y * g1.y + g1.z * g1.z + g1.w * g1.w;
    #pragma unroll
    for (int o = 4; o; o >>= 1) d += __shfl_xor_sync(0xffffffffu, d, o, 8);
    float scale = 1.0f / fmaxf(sqrtf(d), 1e-12f);

    float4* ob = (r < N_USERS) ? (out_u + (size_t)r * VPR)
                               : (out_i + (size_t)(r - N_USERS) * VPR);
    ob[2 * c]     = make_float4(o0 + g0.x * scale, o1 + g0.y * scale,
                                o2 + g0.z * scale, o3 + g0.w * scale);
    ob[2 * c + 1] = make_float4(o4 + g1.x * scale, o5 + g1.y * scale,
                                o6 + g1.z * scale, o7 + g1.w * scale);
}

// -------- host orchestration --------
static inline int gridFor(long long threads, int tpb) {
    return (int)((threads + tpb - 1) / tpb);
}

extern "C" void kernel_launch(void* const* d_in, const int* in_sizes, int n_in,
                              void* d_out, int out_size) {
    const float4* user_emb = (const float4*)d_in[0];
    const float4* item_emb = (const float4*)d_in[1];
    const float4* uu_emb   = (const float4*)d_in[2];
    const float4* ii_emb   = (const float4*)d_in[3];
    const float*  ui_vals  = (const float*)d_in[4];
    const float*  ii_vals  = (const float*)d_in[5];
    const float*  uu_vals  = (const float*)d_in[6];
    const int*    ui_rows  = (const int*)d_in[7];
    const int*    ui_cols  = (const int*)d_in[8];
    const int*    ii_rows  = (const int*)d_in[9];
    const int*    ii_cols  = (const int*)d_in[10];
    const int*    uu_rows  = (const int*)d_in[11];
    const int*    uu_cols  = (const int*)d_in[12];
    const int nnz_ui = in_sizes[7];
    const int nnz_ii = in_sizes[9];
    const int nnz_uu = in_sizes[11];

    float* out = (float*)d_out;
    float4* out_u  = (float4*)out;
    float4* out_i  = (float4*)(out + (size_t)N_USERS * DIM);
    float4* out_ii = (float4*)(out + (size_t)(N_USERS + N_ITEMS) * DIM);
    float4* out_uu = (float4*)(out + (size_t)(N_USERS + 2 * N_ITEMS) * DIM);

    uint4 *p_iih, *p_uuh, *p_ii1h, *p_uu1h, *p_egoh_a, *p_egoh_b;
    cudaGetSymbolAddress((void**)&p_iih,    g_iih);
    cudaGetSymbolAddress((void**)&p_uuh,    g_uuh);
    cudaGetSymbolAddress((void**)&p_ii1h,   g_ii1h);
    cudaGetSymbolAddress((void**)&p_uu1h,   g_uu1h);
    cudaGetSymbolAddress((void**)&p_egoh_a, g_egoh_a);
    cudaGetSymbolAddress((void**)&p_egoh_b, g_egoh_b);
    int *ptr_ui, *ptr_ii, *ptr_uu, *rk_ui, *rk_ii, *rk_uu, *bsum;
    float2 *pk_ui, *pk_ii, *pk_uu;
    unsigned int *arr, *dn;
    cudaGetSymbolAddress((void**)&ptr_ui, g_ptr_ui);
    cudaGetSymbolAddress((void**)&pk_ui,  g_pk_ui);
    cudaGetSymbolAddress((void**)&rk_ui,  g_rk_ui);
    cudaGetSymbolAddress((void**)&ptr_ii, g_ptr_ii);
    cudaGetSymbolAddress((void**)&pk_ii,  g_pk_ii);
    cudaGetSymbolAddress((void**)&rk_ii,  g_rk_ii);
    cudaGetSymbolAddress((void**)&ptr_uu, g_ptr_uu);
    cudaGetSymbolAddress((void**)&pk_uu,  g_pk_uu);
    cudaGetSymbolAddress((void**)&rk_uu,  g_rk_uu);
    cudaGetSymbolAddress((void**)&bsum,   g_bsum);
    cudaGetSymbolAddress((void**)&arr,    g_arr);
    cudaGetSymbolAddress((void**)&dn,     g_dn);

    // one-time host objects (identical launch pattern every call -> deterministic)
    static cudaStream_t sA = nullptr, sB = nullptr;
    static cudaEvent_t  eC = nullptr, eA = nullptr, eB = nullptr;
    if (sA == nullptr) {
        cudaStreamCreateWithFlags(&sA, cudaStreamNonBlocking);
        cudaStreamCreateWithFlags(&sB, cudaStreamNonBlocking);
        cudaEventCreateWithFlags(&eC, cudaEventDisableTiming);
        cudaEventCreateWithFlags(&eA, cudaEventDisableTiming);
        cudaEventCreateWithFlags(&eB, cudaEventDisableTiming);
    }

    const int TPB = 256;

    // ---- stage 0 (main stream): fp16 convert + zero ptr arrays ----
    k_cvt<<<gridFor(CVT_EGO, TPB), TPB>>>(user_emb, item_emb, ii_emb, uu_emb,
                                          p_egoh_a, p_iih, p_uuh,
                                          ptr_ui, ptr_ii, ptr_uu);
    cudaEventRecord(eC, 0);
    cudaStreamWaitEvent(sA, eC, 0);
    cudaStreamWaitEvent(sB, eC, 0);

    // ---- stream A: full ii chain -> out_ii ----
    k_hist<<<gridFor(nnz_ii, 1024), TPB, 0, sA>>>(ii_rows, nnz_ii, ptr_ii, rk_ii);
    k_scan_one<<<NB_II, 1024, 0, sA>>>(ptr_ii, N_ITEMS + 1, bsum + NB_UI,
                                       arr + 1, dn + 1, NB_II);
    k_scatter<<<gridFor(nnz_ii, 1024), TPB, 0, sA>>>(ii_rows, ii_cols, ii_vals,
                                                     ptr_ii, rk_ii, pk_ii, nnz_ii);
    k_spmm_h16<<<B_II, TPB, 0, sA>>>(ptr_ii, pk_ii, p_iih, p_ii1h);
    k_spmm_f32<<<B_II, TPB, 0, sA>>>(ptr_ii, pk_ii, p_ii1h, out_ii);
    cudaEventRecord(eA, sA);

    // ---- stream B: full uu chain -> out_uu ----
    k_hist<<<gridFor(nnz_uu, 1024), TPB, 0, sB>>>(uu_rows, nnz_uu, ptr_uu, rk_uu);
    k_scan_one<<<NB_UU, 1024, 0, sB>>>(ptr_uu, N_USERS + 1, bsum + NB_UI + NB_II,
                                       arr + 2, dn + 2, NB_UU);
    k_scatter<<<gridFor(nnz_uu, 1024), TPB, 0, sB>>>(uu_rows, uu_cols, uu_vals,
                                                     ptr_uu, rk_uu, pk_uu, nnz_uu);
    k_spmm_h16<<<B_UU, TPB, 0, sB>>>(ptr_uu, pk_uu, p_uuh, p_uu1h);
    k_spmm_f32<<<B_UU, TPB, 0, sB>>>(ptr_uu, pk_uu, p_uu1h, out_uu);
    cudaEventRecord(eB, sB);

    // ---- main stream: ui build + layers 1,2 ----
    k_hist<<<gridFor(nnz_ui, 1024), TPB>>>(ui_rows, nnz_ui, ptr_ui, rk_ui);
    k_scan_one<<<NB_UI, 1024>>>(ptr_ui, NTOT + 1, bsum, arr, dn, NB_UI);
    k_scatter<<<gridFor(nnz_ui, 1024), TPB>>>(ui_rows, ui_cols, ui_vals,
                                              ptr_ui, rk_ui, pk_ui, nnz_ui);
    k_spmm_h16<<<B_UI, TPB>>>(ptr_ui, pk_ui, p_egoh_a, p_egoh_b);   // ui1: e0->e1
    k_spmm_h16<<<B_UI, TPB>>>(ptr_ui, pk_ui, p_egoh_b, p_egoh_a);   // ui2: e1->e2

    // ---- join, then fused ui3 + finalize ----
    cudaStreamWaitEvent(0, eA, 0);
    cudaStreamWaitEvent(0, eB, 0);
    k_ui3<<<B_UI, TPB>>>(ptr_ui, pk_ui, p_egoh_a, p_egoh_b,
                         user_emb, item_emb, out_uu, out_ii, out_u, out_i);
}